// round 6
// baseline (speedup 1.0000x reference)
#include <cuda_runtime.h>
#include <cuda_bf16.h>
#include <mma.h>
using namespace nvcuda;

#define BS_ 1024
#define DS_ 128
#define DM_ 256
#define NH_ 4
#define DH_ 32
#define T_ 8
#define NL_ 2
#define VOC_ 32000
#define NBLK 128
#define DECAY_F 0.6065306597126334f
#define SCALE_F 0.17677669529663687f

// ---------------- device state ----------------
__device__ __align__(16) float g_tok[BS_*DM_];
__device__ __align__(16) float g_x[BS_*DM_];
__device__ __align__(16) float g_hbuf[NL_][2][BS_*DS_];
__device__ __align__(16) float g_sv[NL_][BS_*DS_];
__device__ __align__(16) float g_ov[NL_][BS_*DM_];
__device__ __align__(16) float g_kv0[BS_*2*DS_];
__device__ __align__(16) float g_kv[BS_*2*DS_];
__device__ __align__(16) float g_att[BS_*DS_];
__device__ __align__(16) float g_tsum[BS_*DM_];
// transposed weights
__device__ __align__(16) float g_Wqt[NL_][DS_*DS_];     // [k][d]
__device__ __align__(16) float g_At [NL_][DS_*DS_];     // [k][c]
__device__ __align__(16) float g_Wot[NL_][DS_*DS_];     // [k][c]
__device__ __align__(16) float g_Ct [NL_][DS_*DM_];     // [k][c]
__device__ __align__(16) float g_Wkvt[NL_][DM_*2*DS_];  // [k][c]
__device__ float g_ts[NL_], g_to[NL_];
__device__ unsigned int g_cnt1, g_cnt2;
__device__ unsigned int g_bar;
__device__ volatile unsigned int g_sense;

// bf16 split storage for logits
__device__ __align__(16) __nv_bfloat16 g_Whi[(size_t)VOC_*DM_];
__device__ __align__(16) __nv_bfloat16 g_Wlo[(size_t)VOC_*DM_];
__device__ __align__(16) __nv_bfloat16 g_Bext[(size_t)VOC_*32];

// ---------------- fused setup: init + pack + embed + conv_w ----------------
__global__ void setup_kernel(const int* __restrict__ ids, const float* __restrict__ emb,
                             const float* __restrict__ Wq, const float* __restrict__ Amat,
                             const float* __restrict__ Wo, const float* __restrict__ Cmat,
                             const float* __restrict__ Wkv,
                             const float* __restrict__ Wout, const float* __restrict__ bout) {
    int idx = blockIdx.x * blockDim.x + threadIdx.x;
    int stride = gridDim.x * blockDim.x;
    // --- init state ---
    {
        float* h  = &g_hbuf[0][0][0];
        float* sv = &g_sv[0][0];
        float* ov = &g_ov[0][0];
        for (int i = idx; i < NL_*2*BS_*DS_; i += stride) h[i] = 0.f;
        for (int i = idx; i < NL_*BS_*DS_;  i += stride) sv[i] = 0.f;
        for (int i = idx; i < NL_*BS_*DM_;  i += stride) ov[i] = 0.f;
        for (int i = idx; i < BS_*DM_;      i += stride) g_tsum[i] = 0.f;
        if (idx == 0) {
            g_ts[0] = g_ts[1] = 1.0f;
            g_to[0] = g_to[1] = 1.0f;
            g_cnt1 = 0u; g_cnt2 = 0u;
            g_bar = 0u; g_sense = 0u;
        }
    }
    // --- embed ---
    for (int i = idx; i < BS_*DM_; i += stride) {
        int row = i >> 8, j = i & 255;
        g_tok[i] = emb[(size_t)ids[row]*DM_ + j];
    }
    // --- pack transposed weights ---
    for (int i = idx; i < NL_*DS_*DS_; i += stride) {
        int l = i / (DS_*DS_), rem = i % (DS_*DS_);
        int k = rem / DS_, d = rem % DS_;
        g_Wqt[l][rem] = Wq[l*DS_*DS_ + d*DS_ + k];
        g_At [l][rem] = Amat[l*DS_*DS_ + d*DS_ + k];
        g_Wot[l][rem] = Wo[l*DS_*DS_ + d*DS_ + k];
    }
    for (int i = idx; i < NL_*DS_*DM_; i += stride) {
        int l = i / (DS_*DM_), rem = i % (DS_*DM_);
        int k = rem / DM_, c = rem % DM_;
        g_Ct[l][rem] = Cmat[l*DM_*DS_ + c*DS_ + k];
    }
    for (int i = idx; i < NL_*DM_*2*DS_; i += stride) {
        int l = i / (DM_*2*DS_), rem = i % (DM_*2*DS_);
        int k = rem / (2*DS_), c = rem % (2*DS_);
        g_Wkvt[l][rem] = Wkv[l*2*DS_*DM_ + c*DM_ + k];
    }
    // --- conv_w (bf16 hi/lo split) ---
    {
        const int tot4 = VOC_ * DM_ / 4;
        for (int i = idx; i < tot4; i += stride) {
            float4 w = reinterpret_cast<const float4*>(Wout)[i];
            __nv_bfloat16 hb[4], lb[4];
            hb[0] = __float2bfloat16(w.x); lb[0] = __float2bfloat16(w.x - __bfloat162float(hb[0]));
            hb[1] = __float2bfloat16(w.y); lb[1] = __float2bfloat16(w.y - __bfloat162float(hb[1]));
            hb[2] = __float2bfloat16(w.z); lb[2] = __float2bfloat16(w.z - __bfloat162float(hb[2]));
            hb[3] = __float2bfloat16(w.w); lb[3] = __float2bfloat16(w.w - __bfloat162float(hb[3]));
            reinterpret_cast<uint2*>(g_Whi)[i] = *reinterpret_cast<uint2*>(hb);
            reinterpret_cast<uint2*>(g_Wlo)[i] = *reinterpret_cast<uint2*>(lb);
        }
        for (int n = idx; n < VOC_; n += stride) {
            float b = bout[n];
            __nv_bfloat16 buf[16];
            buf[0] = __float2bfloat16(b);
            buf[1] = __float2bfloat16(b - __bfloat162float(buf[0]));
#pragma unroll
            for (int c = 2; c < 16; c++) buf[c] = __float2bfloat16(0.f);
            uint4* dst = reinterpret_cast<uint4*>(&g_Bext[(size_t)n*32]);
            dst[0] = reinterpret_cast<uint4*>(buf)[0];
            dst[1] = reinterpret_cast<uint4*>(buf)[1];
            uint4 z; z.x = z.y = z.z = z.w = 0u;
            dst[2] = z; dst[3] = z;
        }
    }
}

// ================= persistent megakernel =================
__device__ __forceinline__ void gridbar(unsigned target) {
    __syncthreads();
    if (threadIdx.x == 0) {
        __threadfence();
        unsigned old = atomicAdd(&g_bar, 1u);
        if (old == NBLK - 1u) {
            g_bar = 0u;
            __threadfence();
            atomicExch((unsigned int*)&g_sense, target);
        } else {
            while (g_sense < target) {}
            __threadfence();
        }
    }
    __syncthreads();
}

struct SmA { float Qs[32][36]; float Ks[64][36]; float Vs[64][36]; float Ps[32][68];
             short ql[32][128]; int qcnt[32]; };
struct SmD { float As[16][32]; float Ws[16][32]; short ql[32][128]; int qcnt[32]; };
struct SmKV { short ql[8][256]; int qcnt[8]; };
struct SmE { short ql[8][128]; int qcnt[8]; };
struct SmKV0 { float As[16][32]; float Ws[16][64]; };

// ---- phase: dense kv0 (time-invariant, once) ----
__device__ void ph_kv0(char* smraw, int bid, int tid,
                       const float* __restrict__ Wkv, const float* __restrict__ bkv) {
    SmKV0& S = *reinterpret_cast<SmKV0*>(smraw);
    const int row0 = (bid & 31) * 32;
    const int col0 = (bid >> 5) * 64;
    const int r = tid >> 4;
    const int cj = (tid & 15) * 4;
    float acc[4] = {};
    for (int k0 = 0; k0 < DM_; k0 += 16) {
        __syncthreads();
        if (tid < 128) {
            int lr = tid >> 2, lk = (tid & 3) << 2;
            float4 av = *reinterpret_cast<const float4*>(g_tok + (size_t)(row0+lr)*DM_ + k0 + lk);
            S.As[lk][lr]=av.x; S.As[lk+1][lr]=av.y; S.As[lk+2][lr]=av.z; S.As[lk+3][lr]=av.w;
        } else if (tid < 384) {
            int t2 = tid - 128;
            int lr = t2 >> 2, lk = (t2 & 3) << 2;
            float4 wv = *reinterpret_cast<const float4*>(Wkv + (size_t)(col0+lr)*DM_ + k0 + lk);
            S.Ws[lk][lr]=wv.x; S.Ws[lk+1][lr]=wv.y; S.Ws[lk+2][lr]=wv.z; S.Ws[lk+3][lr]=wv.w;
        }
        __syncthreads();
#pragma unroll
        for (int kk = 0; kk < 16; kk++) {
            float a = S.As[kk][r];
            float4 w = *reinterpret_cast<const float4*>(&S.Ws[kk][cj]);
            acc[0] += a*w.x; acc[1] += a*w.y; acc[2] += a*w.z; acc[3] += a*w.w;
        }
    }
#pragma unroll
    for (int j = 0; j < 4; j++)
        g_kv0[(row0+r)*(2*DS_) + col0 + cj + j] = acc[j] + bkv[col0 + cj + j];
}

// ---- phase: sparse kv for layer 1 ----
__device__ void ph_kv(char* smraw, int bid, int tid, const float* __restrict__ bkv) {
    SmKV& S = *reinterpret_cast<SmKV*>(smraw);
    const int row0 = bid * 8;
    const int wrp = tid >> 5, lane = tid & 31;
    if (wrp < 8) {
        int base = 0;
        const float* xr = g_x + (size_t)(row0 + wrp) * DM_;
#pragma unroll
        for (int c4 = 0; c4 < 8; c4++) {
            float v = xr[c4*32 + lane];
            unsigned mask = __ballot_sync(0xffffffffu, v != 0.f);
            if (v != 0.f)
                S.ql[wrp][base + __popc(mask & ((1u<<lane)-1u))] = (short)(c4*32 + lane);
            base += __popc(mask);
        }
        if (lane == 0) S.qcnt[wrp] = base;
    }
    __syncthreads();
    const int c = tid & 255;
    const int r0 = (tid >> 8) * 4;
    const float* wt = g_Wkvt[1] + c;
    const float bias = bkv[2*DS_ + c];
#pragma unroll 1
    for (int r = r0; r < r0 + 4; r++) {
        float acc = 0.f;
        int cnt = S.qcnt[r];
        const short* lst = S.ql[r];
        for (int i = 0; i < cnt; i++)
            acc += wt[(int)lst[i] * (2*DS_)];
        g_kv[(row0 + r) * (2*DS_) + c] = acc + bias;
    }
}

// ---- phase: flash attention + fused sparse q + threshold update ----
__device__ void ph_attn(char* smraw, int bid, int tid, int l, int prev_l, int par,
                        const float* __restrict__ bq) {
    SmA& S = *reinterpret_cast<SmA*>(smraw);
    const int head = bid & 3;
    const int q0 = (bid >> 2) * 32;
    const float* kvsrc = (l == 0) ? g_kv0 : g_kv;
    const float* hsrc = g_hbuf[l][par];

    if (prev_l >= 0 && bid == 0 && tid == 0) {
        float e1 = (float)g_cnt1 / (float)(BS_*DS_) - 0.02f;
        g_ts[prev_l] = fmaxf(g_ts[prev_l] + 0.1f*e1, 0.5f);
        float e2 = (float)g_cnt2 / (float)(BS_*DM_) - 0.02f;
        g_to[prev_l] = fmaxf(g_to[prev_l] + 0.1f*e2, 0.5f);
        g_cnt1 = 0u; g_cnt2 = 0u;
    }

    {
        const int wrp = tid >> 5, lane = tid & 31;
#pragma unroll
        for (int rr = 0; rr < 2; rr++) {
            int r = wrp*2 + rr;
            int base = 0;
            const float* hr = hsrc + (size_t)(q0+r)*DS_;
#pragma unroll
            for (int c4 = 0; c4 < 4; c4++) {
                float v = hr[c4*32 + lane];
                unsigned mask = __ballot_sync(0xffffffffu, v != 0.f);
                if (v != 0.f)
                    S.ql[r][base + __popc(mask & ((1u<<lane)-1u))] = (short)(c4*32 + lane);
                base += __popc(mask);
            }
            if (lane == 0) S.qcnt[r] = base;
        }
    }
    __syncthreads();

    const int r = tid >> 4;
    const int lane = tid & 15;
    const int d0 = lane * 2;

    {
        float a0 = 0.f, a1 = 0.f;
        int cnt = S.qcnt[r];
        const float* wt = g_Wqt[l] + head*DH_ + d0;
        for (int i = 0; i < cnt; i++) {
            float2 w = *reinterpret_cast<const float2*>(wt + (int)S.ql[r][i]*DS_);
            a0 += w.x; a1 += w.y;
        }
        S.Qs[r][d0]   = a0 + bq[l*DS_ + head*DH_ + d0];
        S.Qs[r][d0+1] = a1 + bq[l*DS_ + head*DH_ + d0 + 1];
    }

    float m = -INFINITY, lsum = 0.f;
    float o0a = 0.f, o0b = 0.f, o1a = 0.f, o1b = 0.f;

    for (int kt = 0; kt < 16; kt++) {
        __syncthreads();
        for (int i = tid; i < 64*32; i += 512) {
            int kr = i >> 5, d = i & 31;
            int key = kt*64 + kr;
            S.Ks[kr][d] = kvsrc[key*(2*DS_) + head*DH_ + d];
            S.Vs[kr][d] = kvsrc[key*(2*DS_) + DS_ + head*DH_ + d];
        }
        __syncthreads();

        float s[4] = {0.f, 0.f, 0.f, 0.f};
#pragma unroll
        for (int d4 = 0; d4 < 8; d4++) {
            float4 q = *reinterpret_cast<const float4*>(&S.Qs[r][d4*4]);
#pragma unroll
            for (int kk = 0; kk < 4; kk++) {
                float4 k4 = *reinterpret_cast<const float4*>(&S.Ks[lane + kk*16][d4*4]);
                s[kk] += q.x*k4.x + q.y*k4.y + q.z*k4.z + q.w*k4.w;
            }
        }
        float tmax = -INFINITY;
#pragma unroll
        for (int kk = 0; kk < 4; kk++) { s[kk] *= SCALE_F; tmax = fmaxf(tmax, s[kk]); }
#pragma unroll
        for (int off = 8; off > 0; off >>= 1)
            tmax = fmaxf(tmax, __shfl_xor_sync(0xffffffffu, tmax, off));
        float mnew = fmaxf(m, tmax);
        float corr = __expf(m - mnew);
        float psum = 0.f;
#pragma unroll
        for (int kk = 0; kk < 4; kk++) {
            float p = __expf(s[kk] - mnew);
            S.Ps[r][lane + kk*16] = p;
            psum += p;
        }
#pragma unroll
        for (int off = 8; off > 0; off >>= 1)
            psum += __shfl_xor_sync(0xffffffffu, psum, off);
        lsum = lsum * corr + psum;
        m = mnew;
        o0a *= corr; o0b *= corr; o1a *= corr; o1b *= corr;
        __syncwarp();
#pragma unroll
        for (int key = 0; key < 64; key += 2) {
            float p0 = S.Ps[r][key];
            float p1 = S.Ps[r][key+1];
            float2 v0 = *reinterpret_cast<const float2*>(&S.Vs[key][d0]);
            float2 v1 = *reinterpret_cast<const float2*>(&S.Vs[key+1][d0]);
            o0a += p0*v0.x; o1a += p0*v0.y;
            o0b += p1*v1.x; o1b += p1*v1.y;
        }
    }
    float inv = 1.f / lsum;
    float* dst = &g_att[(q0+r)*DS_ + head*DH_ + d0];
    dst[0] = (o0a + o0b)*inv; dst[1] = (o1a + o1b)*inv;
}

// ---- phase: upd = st(sparse) + att@Wo.T + bo ; LIF1 ----
__device__ void ph_d(char* smraw, int* sred, int bid, int tid, int l, int par,
                     const float* __restrict__ bo) {
    SmD& S = *reinterpret_cast<SmD*>(smraw);
    const int col0 = (bid & 3) * 32;
    const int row0 = (bid >> 2) * 32;
    const float* hsrc = g_hbuf[l][par];
    float* hdst = g_hbuf[l][1 - par];

    {
        const int wrp = tid >> 5, lane = tid & 31;
#pragma unroll
        for (int rr = 0; rr < 2; rr++) {
            int r = wrp*2 + rr;
            int base = 0;
            const float* hr = hsrc + (size_t)(row0+r)*DS_;
#pragma unroll
            for (int c4 = 0; c4 < 4; c4++) {
                float v = hr[c4*32 + lane];
                unsigned mask = __ballot_sync(0xffffffffu, v != 0.f);
                if (v != 0.f)
                    S.ql[r][base + __popc(mask & ((1u<<lane)-1u))] = (short)(c4*32 + lane);
                base += __popc(mask);
            }
            if (lane == 0) S.qcnt[r] = base;
        }
    }

    const int rr = tid >> 5;          // 0..15
    const int c  = tid & 31;
    float acc0 = 0.f, acc1 = 0.f;
    for (int k0 = 0; k0 < DS_; k0 += 16) {
        __syncthreads();
        if (tid < 256) {
            int lr = tid >> 3, lk = (tid & 7) << 1;
            float2 av = *reinterpret_cast<const float2*>(g_att + (size_t)(row0+lr)*DS_ + k0 + lk);
            S.As[lk][lr] = av.x; S.As[lk+1][lr] = av.y;
        } else {
            int t2 = tid - 256;
            int cc = t2 & 31, kk = (t2 >> 5) << 1;
            S.Ws[kk][cc]   = g_Wot[l][(size_t)(k0+kk)*DS_ + col0 + cc];
            S.Ws[kk+1][cc] = g_Wot[l][(size_t)(k0+kk+1)*DS_ + col0 + cc];
        }
        __syncthreads();
#pragma unroll
        for (int kk = 0; kk < 16; kk++) {
            float w = S.Ws[kk][c];
            acc0 += S.As[kk][rr] * w;
            acc1 += S.As[kk][rr+16] * w;
        }
    }
    float thr = g_ts[l];
    int spikes = 0;
#pragma unroll
    for (int ii = 0; ii < 2; ii++) {
        int rloc = (ii == 0) ? rr : rr + 16;
        float st = 0.f;
        {
            int cnt = S.qcnt[rloc];
            const short* lst = S.ql[rloc];
            const float* at = g_At[l] + col0 + c;
            for (int i2 = 0; i2 < cnt; i2++)
                st += at[(int)lst[i2] * DS_];
        }
        float acc = (ii == 0) ? acc0 : acc1;
        int r = row0 + rloc;
        int ci = col0 + c;
        float upd = acc + bo[l*DS_ + ci] + st;
        float v = g_sv[l][r*DS_ + ci] * DECAY_F + upd;
        float sp = (v >= thr) ? 1.f : 0.f;
        hdst[r*DS_ + ci] = sp;
        g_sv[l][r*DS_ + ci] = v * (1.f - sp);
        spikes += (v >= thr) ? 1 : 0;
    }
    sred[tid] = spikes; __syncthreads();
    for (int s = 256; s > 0; s >>= 1) { if (tid < s) sred[tid] += sred[tid+s]; __syncthreads(); }
    if (tid == 0) atomicAdd(&g_cnt1, (unsigned)sred[0]);
}

// ---- phase: out_pot = h2@C.T (sparse) ; LIF2 ----
__device__ void ph_e(char* smraw, int* sred, int bid, int tid, int l, int par) {
    SmE& S = *reinterpret_cast<SmE*>(smraw);
    const int row0 = bid * 8;
    const float* hnew = g_hbuf[l][1 - par];
    const int wrp = tid >> 5, lane = tid & 31;
    if (wrp < 8) {
        int base = 0;
        const float* hr = hnew + (size_t)(row0 + wrp)*DS_;
#pragma unroll
        for (int c4 = 0; c4 < 4; c4++) {
            float v = hr[c4*32 + lane];
            unsigned mask = __ballot_sync(0xffffffffu, v != 0.f);
            if (v != 0.f)
                S.ql[wrp][base + __popc(mask & ((1u<<lane)-1u))] = (short)(c4*32 + lane);
            base += __popc(mask);
        }
        if (lane == 0) S.qcnt[wrp] = base;
    }
    __syncthreads();
    const int c = tid & 255;
    const int r0 = (tid >> 8) * 4;
    const float* ct = g_Ct[l] + c;
    float thr = g_to[l];
    int spikes = 0;
#pragma unroll 1
    for (int r = r0; r < r0 + 4; r++) {
        float acc = 0.f;
        int cnt = S.qcnt[r];
        const short* lst = S.ql[r];
        for (int i = 0; i < cnt; i++)
            acc += ct[(int)lst[i] * DM_];
        int gi = (row0 + r)*DM_ + c;
        float v = g_ov[l][gi] * DECAY_F + acc;
        float sp = (v >= thr) ? 1.f : 0.f;
        g_ov[l][gi] = v * (1.f - sp);
        if (l == 0) g_x[gi] = sp;
        else        g_tsum[gi] += sp * 0.125f;
        spikes += (v >= thr) ? 1 : 0;
    }
    sred[tid] = spikes; __syncthreads();
    for (int s = 256; s > 0; s >>= 1) { if (tid < s) sred[tid] += sred[tid+s]; __syncthreads(); }
    if (tid == 0) atomicAdd(&g_cnt2, (unsigned)sred[0]);
}

__global__ void __launch_bounds__(512, 1)
mega_kernel(const float* __restrict__ bq, const float* __restrict__ bkv,
            const float* __restrict__ bo, const float* __restrict__ Wkv) {
    __shared__ __align__(16) char smraw[sizeof(SmA)];
    __shared__ int sred[512];
    const int bid = blockIdx.x;
    const int tid = threadIdx.x;
    unsigned bt = 0;
    int prev_l = -1;

    ph_kv0(smraw, bid, tid, Wkv, bkv);
    gridbar(++bt);

    for (int t = 0; t < T_; t++) {
        int par = t & 1;
        for (int l = 0; l < NL_; l++) {
            if (l == 1) { ph_kv(smraw, bid, tid, bkv); gridbar(++bt); }
            ph_attn(smraw, bid, tid, l, prev_l, par, bq);
            gridbar(++bt);
            ph_d(smraw, sred, bid, tid, l, par, bo);
            gridbar(++bt);
            ph_e(smraw, sred, bid, tid, l, par);
            gridbar(++bt);
            prev_l = l;
        }
    }
}

// ---------------- logits via bf16 split tensor cores (A converted inline) ----------------
__global__ void __launch_bounds__(256)
k_logits_mma(float* __restrict__ out) {
    __shared__ __align__(16) __nv_bfloat16 As[128][48];
    __shared__ __align__(16) __nv_bfloat16 Bs[128][48];
    const int tid = threadIdx.x;
    const int wid = tid >> 5;
    const int wm = wid & 1;
    const int wn = wid >> 1;
    const int row0 = blockIdx.x * 128;
    const int col0 = blockIdx.y * 128;

    wmma::fragment<wmma::accumulator, 16, 16, 16, float> acc[4][2];
#pragma unroll
    for (int i = 0; i < 4; i++)
#pragma unroll
        for (int j = 0; j < 2; j++)
            wmma::fill_fragment(acc[i][j], 0.f);

    const int lr = tid >> 1;
    const int lh = (tid & 1) * 16;

    for (int c = 0; c < 17; c++) {
        __nv_bfloat16 abuf[16];
        uint4 b0, b1;
        if (c < 16) {
            int koff = (c & 7) * 32;
            const float* af = g_tsum + (size_t)(row0+lr)*DM_ + koff + lh;
#pragma unroll
            for (int u = 0; u < 4; u++) {
                float4 f = *reinterpret_cast<const float4*>(af + u*4);
                abuf[u*4+0] = __float2bfloat16(f.x);
                abuf[u*4+1] = __float2bfloat16(f.y);
                abuf[u*4+2] = __float2bfloat16(f.z);
                abuf[u*4+3] = __float2bfloat16(f.w);
            }
            const __nv_bfloat16* bsrc = ((c < 8) ? g_Whi : g_Wlo) + (size_t)(col0+lr)*DM_ + koff + lh;
            b0 = *reinterpret_cast<const uint4*>(bsrc);
            b1 = *reinterpret_cast<const uint4*>(bsrc + 8);
        } else {
            // A ones-chunk: cols 0,1 = 1.0, rest 0 (bias fold)
#pragma unroll
            for (int u = 0; u < 16; u++) abuf[u] = __float2bfloat16(0.f);
            if (lh == 0) { abuf[0] = __float2bfloat16(1.f); abuf[1] = __float2bfloat16(1.f); }
            const __nv_bfloat16* bsrc = g_Bext + (size_t)(col0+lr)*32 + lh;
            b0 = *reinterpret_cast<const uint4*>(bsrc);
            b1 = *reinterpret_cast<const uint4*>(bsrc + 8);
        }
        __syncthreads();
        *reinterpret_cast<uint4*>(&As[lr][lh])     = reinterpret_cast<uint4*>(abuf)[0];
        *reinterpret_cast<uint4*>(&As[lr][lh + 8]) = reinterpret_cast<uint4*>(abuf)[1];
        *reinterpret_cast<uint4*>(&Bs[lr][lh])     = b0;
        *reinterpret_cast<uint4*>(&Bs[lr][lh + 8]) = b1;
        __syncthreads();
#pragma unroll
        for (int kk = 0; kk < 32; kk += 16) {
            wmma::fragment<wmma::matrix_a, 16, 16, 16, __nv_bfloat16, wmma::row_major> af[4];
            wmma::fragment<wmma::matrix_b, 16, 16, 16, __nv_bfloat16, wmma::col_major> bf[2];
#pragma unroll
            for (int i = 0; i < 4; i++)
                wmma::load_matrix_sync(af[i], &As[wm*64 + i*16][kk], 48);
#pragma unroll
            for (int j = 0; j < 2; j++)
                wmma::load_matrix_sync(bf[j], &Bs[wn*32 + j*16][kk], 48);
#pragma unroll
            for (int i = 0; i < 4; i++)
#pragma unroll
                for (int j = 0; j < 2; j++)
                    wmma::mma_sync(acc[i][j], af[i], bf[j], acc[i][j]);
        }
    }
#pragma unroll
    for (int i = 0; i < 4; i++)
#pragma unroll
        for (int j = 0; j < 2; j++) {
            size_t r = row0 + wm*64 + i*16;
            size_t cc = col0 + wn*32 + j*16;
            wmma::store_matrix_sync(&out[r*VOC_ + cc], acc[i][j], VOC_, wmma::mem_row_major);
        }
}

// ---------------- launch ----------------
extern "C" void kernel_launch(void* const* d_in, const int* in_sizes, int n_in,
                              void* d_out, int out_size) {
    const int*   ids  = (const int*)d_in[0];
    const float* emb  = (const float*)d_in[1];
    const float* Amat = (const float*)d_in[2];
    const float* Cmat = (const float*)d_in[3];
    const float* Wq   = (const float*)d_in[4];
    const float* bq   = (const float*)d_in[5];
    const float* Wkv  = (const float*)d_in[6];
    const float* bkv  = (const float*)d_in[7];
    const float* Wo   = (const float*)d_in[8];
    const float* bo   = (const float*)d_in[9];
    const float* Wout = (const float*)d_in[10];
    const float* bout = (const float*)d_in[11];
    float* out = (float*)d_out;

    setup_kernel<<<2048, 256>>>(ids, emb, Wq, Amat, Wo, Cmat, Wkv, Wout, bout);
    mega_kernel<<<NBLK, 512>>>(bq, bkv, bo, Wkv);
    k_logits_mma<<<dim3(8, 250), 256>>>(out);
}

// round 7
// speedup vs baseline: 1.1925x; 1.1925x over previous
#include <cuda_runtime.h>
#include <cuda_bf16.h>
#include <mma.h>
using namespace nvcuda;

#define BS_ 1024
#define DS_ 128
#define DM_ 256
#define NH_ 4
#define DH_ 32
#define T_ 8
#define NL_ 2
#define VOC_ 32000
#define DECAY_F 0.6065306597126334f
#define SCALE_F 0.17677669529663687f

// ---------------- device state ----------------
__device__ __align__(16) float g_tok[BS_*DM_];
__device__ __align__(16) float g_x[BS_*DM_];
__device__ __align__(16) float g_hbuf[NL_][2][BS_*DS_];
__device__ __align__(16) float g_sv[NL_][BS_*DS_];
__device__ __align__(16) float g_ov[NL_][BS_*DM_];
__device__ __align__(16) float g_kv0[BS_*2*DS_];
__device__ __align__(16) float g_kv[BS_*2*DS_];
__device__ __align__(16) float g_att[BS_*DS_];
__device__ __align__(16) float g_tsum[BS_*DM_];
// transposed weights
__device__ __align__(16) float g_Wqt[NL_][DS_*DS_];     // [k][d]
__device__ __align__(16) float g_At [NL_][DS_*DS_];     // [k][c]
__device__ __align__(16) float g_Wot[NL_][DS_*DS_];     // [k][c]
__device__ __align__(16) float g_Ct [NL_][DS_*DM_];     // [k][c]
__device__ __align__(16) float g_Wkvt[NL_][DM_*2*DS_];  // [k][c]
__device__ float g_ts[NL_], g_to[NL_];
__device__ unsigned int g_cnt1, g_cnt2;

// bf16 split storage for logits
__device__ __align__(16) __nv_bfloat16 g_Whi[(size_t)VOC_*DM_];
__device__ __align__(16) __nv_bfloat16 g_Wlo[(size_t)VOC_*DM_];
__device__ __align__(16) __nv_bfloat16 g_Bext[(size_t)VOC_*32];

// ---------------- fused setup ----------------
__global__ void setup_kernel(const int* __restrict__ ids, const float* __restrict__ emb,
                             const float* __restrict__ Wq, const float* __restrict__ Amat,
                             const float* __restrict__ Wo, const float* __restrict__ Cmat,
                             const float* __restrict__ Wkv,
                             const float* __restrict__ Wout, const float* __restrict__ bout) {
    int idx = blockIdx.x * blockDim.x + threadIdx.x;
    int stride = gridDim.x * blockDim.x;
    {
        float* h  = &g_hbuf[0][0][0];
        float* sv = &g_sv[0][0];
        float* ov = &g_ov[0][0];
        for (int i = idx; i < NL_*2*BS_*DS_; i += stride) h[i] = 0.f;
        for (int i = idx; i < NL_*BS_*DS_;  i += stride) sv[i] = 0.f;
        for (int i = idx; i < NL_*BS_*DM_;  i += stride) ov[i] = 0.f;
        for (int i = idx; i < BS_*DM_;      i += stride) g_tsum[i] = 0.f;
        if (idx == 0) {
            g_ts[0] = g_ts[1] = 1.0f;
            g_to[0] = g_to[1] = 1.0f;
            g_cnt1 = 0u; g_cnt2 = 0u;
        }
    }
    for (int i = idx; i < BS_*DM_; i += stride) {
        int row = i >> 8, j = i & 255;
        g_tok[i] = emb[(size_t)ids[row]*DM_ + j];
    }
    for (int i = idx; i < NL_*DS_*DS_; i += stride) {
        int l = i / (DS_*DS_), rem = i % (DS_*DS_);
        int k = rem / DS_, d = rem % DS_;
        g_Wqt[l][rem] = Wq[l*DS_*DS_ + d*DS_ + k];
        g_At [l][rem] = Amat[l*DS_*DS_ + d*DS_ + k];
        g_Wot[l][rem] = Wo[l*DS_*DS_ + d*DS_ + k];
    }
    for (int i = idx; i < NL_*DS_*DM_; i += stride) {
        int l = i / (DS_*DM_), rem = i % (DS_*DM_);
        int k = rem / DM_, c = rem % DM_;
        g_Ct[l][rem] = Cmat[l*DM_*DS_ + c*DS_ + k];
    }
    for (int i = idx; i < NL_*DM_*2*DS_; i += stride) {
        int l = i / (DM_*2*DS_), rem = i % (DM_*2*DS_);
        int k = rem / (2*DS_), c = rem % (2*DS_);
        g_Wkvt[l][rem] = Wkv[l*2*DS_*DM_ + c*DM_ + k];
    }
    {
        const int tot4 = VOC_ * DM_ / 4;
        for (int i = idx; i < tot4; i += stride) {
            float4 w = reinterpret_cast<const float4*>(Wout)[i];
            __nv_bfloat16 hb[4], lb[4];
            hb[0] = __float2bfloat16(w.x); lb[0] = __float2bfloat16(w.x - __bfloat162float(hb[0]));
            hb[1] = __float2bfloat16(w.y); lb[1] = __float2bfloat16(w.y - __bfloat162float(hb[1]));
            hb[2] = __float2bfloat16(w.z); lb[2] = __float2bfloat16(w.z - __bfloat162float(hb[2]));
            hb[3] = __float2bfloat16(w.w); lb[3] = __float2bfloat16(w.w - __bfloat162float(hb[3]));
            reinterpret_cast<uint2*>(g_Whi)[i] = *reinterpret_cast<uint2*>(hb);
            reinterpret_cast<uint2*>(g_Wlo)[i] = *reinterpret_cast<uint2*>(lb);
        }
        for (int n = idx; n < VOC_; n += stride) {
            float b = bout[n];
            __nv_bfloat16 buf[16];
            buf[0] = __float2bfloat16(b);
            buf[1] = __float2bfloat16(b - __bfloat162float(buf[0]));
#pragma unroll
            for (int c = 2; c < 16; c++) buf[c] = __float2bfloat16(0.f);
            uint4* dst = reinterpret_cast<uint4*>(&g_Bext[(size_t)n*32]);
            dst[0] = reinterpret_cast<uint4*>(buf)[0];
            dst[1] = reinterpret_cast<uint4*>(buf)[1];
            uint4 z; z.x = z.y = z.z = z.w = 0u;
            dst[2] = z; dst[3] = z;
        }
    }
}

// ---------------- dense kv for layer 0 (once) ----------------
__global__ void __launch_bounds__(512)
k_kv0(const float* __restrict__ Wkv, const float* __restrict__ bkv) {
    __shared__ __align__(16) float As[16][64];
    __shared__ __align__(16) float Ws[16][64];
    const int tid = threadIdx.x;
    const int row0 = blockIdx.y*64, col0 = blockIdx.x*64;
    const int ty = tid >> 4;
    const int tx = tid & 15;
    float acc[2][4] = {};
    for (int k0 = 0; k0 < DM_; k0 += 16) {
        if (tid < 256) {
            int lr = tid >> 2, lk = (tid & 3) << 2;
            float4 av = *reinterpret_cast<const float4*>(g_tok + (size_t)(row0+lr)*DM_ + k0 + lk);
            As[lk+0][lr]=av.x; As[lk+1][lr]=av.y; As[lk+2][lr]=av.z; As[lk+3][lr]=av.w;
        } else {
            int t2 = tid - 256;
            int lr = t2 >> 2, lk = (t2 & 3) << 2;
            float4 wv = *reinterpret_cast<const float4*>(Wkv + (size_t)(col0+lr)*DM_ + k0 + lk);
            Ws[lk+0][lr]=wv.x; Ws[lk+1][lr]=wv.y; Ws[lk+2][lr]=wv.z; Ws[lk+3][lr]=wv.w;
        }
        __syncthreads();
#pragma unroll
        for (int kk = 0; kk < 16; kk++) {
            float2 a = *reinterpret_cast<const float2*>(&As[kk][ty*2]);
            float4 w = *reinterpret_cast<const float4*>(&Ws[kk][tx*4]);
            acc[0][0]+=a.x*w.x; acc[0][1]+=a.x*w.y; acc[0][2]+=a.x*w.z; acc[0][3]+=a.x*w.w;
            acc[1][0]+=a.y*w.x; acc[1][1]+=a.y*w.y; acc[1][2]+=a.y*w.z; acc[1][3]+=a.y*w.w;
        }
        __syncthreads();
    }
#pragma unroll
    for (int i = 0; i < 2; i++) {
        int r = row0 + ty*2 + i;
#pragma unroll
        for (int j = 0; j < 4; j++) {
            int c = col0 + tx*4 + j;
            g_kv0[r*(2*DS_) + c] = acc[i][j] + bkv[c];
        }
    }
}

// ---------------- sparse kv for layer 1 ----------------
__global__ void __launch_bounds__(256)
k_kv_sp(const float* __restrict__ bkv) {
    __shared__ short ql[8][256];
    __shared__ int qcnt[8];
    const int tid = threadIdx.x;
    const int row0 = blockIdx.x * 8;
    const int wrp = tid >> 5, lane = tid & 31;
    {
        int base = 0;
        const float* xr = g_x + (size_t)(row0 + wrp) * DM_;
#pragma unroll
        for (int c4 = 0; c4 < 8; c4++) {
            float v = xr[c4*32 + lane];
            unsigned mask = __ballot_sync(0xffffffffu, v != 0.f);
            if (v != 0.f)
                ql[wrp][base + __popc(mask & ((1u<<lane)-1u))] = (short)(c4*32 + lane);
            base += __popc(mask);
        }
        if (lane == 0) qcnt[wrp] = base;
    }
    __syncthreads();
    const int c = tid;
    const float* wt = g_Wkvt[1] + c;
    const float bias = bkv[2*DS_ + c];
#pragma unroll 1
    for (int r = 0; r < 8; r++) {
        float acc = 0.f;
        int cnt = qcnt[r];
        const short* lst = ql[r];
        for (int i = 0; i < cnt; i++)
            acc += wt[(int)lst[i] * (2*DS_)];
        g_kv[(row0 + r) * (2*DS_) + c] = acc + bias;
    }
}

// ---------------- flash attention: register-K QK, tiled PV, fused sparse q ----------------
__global__ void __launch_bounds__(512)
k_attn(int l, int prev_l, int par, const float* __restrict__ bq) {
    __shared__ __align__(16) float Qs[32][36];
    __shared__ __align__(16) float Ks[64][36];
    __shared__ __align__(16) float Vs[64][36];
    __shared__ __align__(16) float Ps[32][68];
    __shared__ float corrs[32], invs[32];
    __shared__ short ql[32][128];
    __shared__ int qcnt[32];
    const int tid = threadIdx.x;
    const int head = blockIdx.y;
    const int q0 = blockIdx.x * 32;
    const float* kvsrc = (l == 0) ? g_kv0 : g_kv;
    const float* hsrc = g_hbuf[l][par];

    // threshold update fold for previous (t,l) pair
    if (prev_l >= 0 && blockIdx.x == 0 && blockIdx.y == 0 && tid == 0) {
        float e1 = (float)g_cnt1 / (float)(BS_*DS_) - 0.02f;
        g_ts[prev_l] = fmaxf(g_ts[prev_l] + 0.1f*e1, 0.5f);
        float e2 = (float)g_cnt2 / (float)(BS_*DM_) - 0.02f;
        g_to[prev_l] = fmaxf(g_to[prev_l] + 0.1f*e2, 0.5f);
        g_cnt1 = 0u; g_cnt2 = 0u;
    }

    // sparse lists: 16 warps x 2 rows
    {
        const int wrp = tid >> 5, lane = tid & 31;
#pragma unroll
        for (int rr = 0; rr < 2; rr++) {
            int r = wrp*2 + rr;
            int base = 0;
            const float* hr = hsrc + (size_t)(q0+r)*DS_;
#pragma unroll
            for (int c4 = 0; c4 < 4; c4++) {
                float v = hr[c4*32 + lane];
                unsigned mask = __ballot_sync(0xffffffffu, v != 0.f);
                if (v != 0.f)
                    ql[r][base + __popc(mask & ((1u<<lane)-1u))] = (short)(c4*32 + lane);
                base += __popc(mask);
            }
            if (lane == 0) qcnt[r] = base;
        }
    }
    __syncthreads();

    const int r = tid >> 4;            // softmax row
    const int lane = tid & 15;
    const int d0 = lane * 2;

    // sparse q = h @ Wq.T + bq (ascending k; identical to R4)
    {
        float a0 = 0.f, a1 = 0.f;
        int cnt = qcnt[r];
        const float* wt = g_Wqt[l] + head*DH_ + d0;
        for (int i = 0; i < cnt; i++) {
            float2 w = *reinterpret_cast<const float2*>(wt + (int)ql[r][i]*DS_);
            a0 += w.x; a1 += w.y;
        }
        Qs[r][d0]   = a0 + bq[l*DS_ + head*DH_ + d0];
        Qs[r][d0+1] = a1 + bq[l*DS_ + head*DH_ + d0 + 1];
    }

    // QK mapping: warp = (qq, key-half); lane = key within half
    const int w  = tid >> 5, wl = tid & 31;
    const int qq = w >> 1;                 // 0..7 -> q rows qq*4..qq*4+3
    const int key_w = (w & 1) * 32 + wl;   // 0..63

    // PV mapping: threads 0..127, 4 rows x 2 dims each
    const bool pv_on = (tid < 128);
    const int pr0 = (tid >> 4) * 4;        // rows pr0..pr0+3
    const int pd0 = (tid & 15) * 2;

    float m = -INFINITY, lsum = 0.f;
    float oa[4][2] = {}, ob[4][2] = {};

    for (int kt = 0; kt < 16; kt++) {
        __syncthreads();
        for (int i = tid; i < 64*32; i += 512) {
            int kr = i >> 5, d = i & 31;
            int key = kt*64 + kr;
            Ks[kr][d] = kvsrc[key*(2*DS_) + head*DH_ + d];
            Vs[kr][d] = kvsrc[key*(2*DS_) + DS_ + head*DH_ + d];
        }
        __syncthreads();

        // QK: K into registers once, 4 q-rows per warp via broadcast
        {
            float4 kr4[8];
#pragma unroll
            for (int d4 = 0; d4 < 8; d4++)
                kr4[d4] = *reinterpret_cast<const float4*>(&Ks[key_w][d4*4]);
#pragma unroll
            for (int q = 0; q < 4; q++) {
                int row = qq*4 + q;
                float s = 0.f;
#pragma unroll
                for (int d4 = 0; d4 < 8; d4++) {
                    float4 qv = *reinterpret_cast<const float4*>(&Qs[row][d4*4]);
                    s += qv.x*kr4[d4].x + qv.y*kr4[d4].y + qv.z*kr4[d4].z + qv.w*kr4[d4].w;
                }
                Ps[row][key_w] = s;
            }
        }
        __syncthreads();

        // softmax (identical math/order to R4)
        float s4[4];
#pragma unroll
        for (int kk = 0; kk < 4; kk++) s4[kk] = Ps[r][lane + kk*16];
        float tmax = -INFINITY;
#pragma unroll
        for (int kk = 0; kk < 4; kk++) { s4[kk] *= SCALE_F; tmax = fmaxf(tmax, s4[kk]); }
#pragma unroll
        for (int off = 8; off > 0; off >>= 1)
            tmax = fmaxf(tmax, __shfl_xor_sync(0xffffffffu, tmax, off));
        float mnew = fmaxf(m, tmax);
        float corr = __expf(m - mnew);
        float psum = 0.f;
#pragma unroll
        for (int kk = 0; kk < 4; kk++) {
            float p = __expf(s4[kk] - mnew);
            Ps[r][lane + kk*16] = p;
            psum += p;
        }
#pragma unroll
        for (int off = 8; off > 0; off >>= 1)
            psum += __shfl_xor_sync(0xffffffffu, psum, off);
        lsum = lsum * corr + psum;
        m = mnew;
        if (lane == 0) corrs[r] = corr;
        __syncthreads();

        // PV: 4 rows x 2 dims per thread; even/odd key chains identical to R4
        if (pv_on) {
#pragma unroll
            for (int q = 0; q < 4; q++) {
                float cc = corrs[pr0 + q];
                oa[q][0] *= cc; oa[q][1] *= cc;
                ob[q][0] *= cc; ob[q][1] *= cc;
            }
#pragma unroll
            for (int key = 0; key < 64; key += 2) {
                float2 v0 = *reinterpret_cast<const float2*>(&Vs[key][pd0]);
                float2 v1 = *reinterpret_cast<const float2*>(&Vs[key+1][pd0]);
#pragma unroll
                for (int q = 0; q < 4; q++) {
                    float p0 = Ps[pr0+q][key];
                    float p1 = Ps[pr0+q][key+1];
                    oa[q][0] += p0*v0.x; oa[q][1] += p0*v0.y;
                    ob[q][0] += p1*v1.x; ob[q][1] += p1*v1.y;
                }
            }
        }
    }
    if (lane == 0) invs[r] = 1.f / lsum;
    __syncthreads();
    if (pv_on) {
#pragma unroll
        for (int q = 0; q < 4; q++) {
            int row = pr0 + q;
            float inv = invs[row];
            float* dst = &g_att[(q0+row)*DS_ + head*DH_ + pd0];
            dst[0] = (oa[q][0] + ob[q][0]) * inv;
            dst[1] = (oa[q][1] + ob[q][1]) * inv;
        }
    }
}

// ---------------- upd = st(sparse) + att@Wo.T + bo ; LIF1 (full staging) ----------------
__global__ void __launch_bounds__(256)
k_d(int l, int par, const float* __restrict__ bo) {
    __shared__ __align__(16) float Att[32][128];
    __shared__ __align__(16) float Wos[128][32];
    __shared__ short ql[32][128];
    __shared__ int qcnt[32];
    __shared__ int sred[256];
    const int tid = threadIdx.x;
    const int col0 = (blockIdx.x) * 32;
    const int row0 = blockIdx.y * 32;
    const float* hsrc = g_hbuf[l][par];
    float* hdst = g_hbuf[l][1 - par];

    // stage Att tile (32x128) and Wo tile (128x32, from transposed g_Wot)
    for (int i = tid; i < 32*32; i += 256) {
        int rr = i >> 5, c4 = (i & 31) * 4;
        *reinterpret_cast<float4*>(&Att[rr][c4]) =
            *reinterpret_cast<const float4*>(g_att + (size_t)(row0+rr)*DS_ + c4);
    }
    for (int i = tid; i < 128*8; i += 256) {
        int k = i >> 3, c4 = (i & 7) * 4;
        *reinterpret_cast<float4*>(&Wos[k][c4]) =
            *reinterpret_cast<const float4*>(g_Wot[l] + (size_t)k*DS_ + col0 + c4);
    }
    // sparse lists: 8 warps x 4 rows
    {
        const int wrp = tid >> 5, lane = tid & 31;
#pragma unroll
        for (int rr = 0; rr < 4; rr++) {
            int r = wrp*4 + rr;
            int base = 0;
            const float* hr = hsrc + (size_t)(row0+r)*DS_;
#pragma unroll
            for (int c4 = 0; c4 < 4; c4++) {
                float v = hr[c4*32 + lane];
                unsigned mask = __ballot_sync(0xffffffffu, v != 0.f);
                if (v != 0.f)
                    ql[r][base + __popc(mask & ((1u<<lane)-1u))] = (short)(c4*32 + lane);
                base += __popc(mask);
            }
            if (lane == 0) qcnt[r] = base;
        }
    }
    __syncthreads();

    const int c = tid & 31;            // column within tile
    const int rq = tid >> 5;           // 0..7 -> rows rq*4..rq*4+3
    float acc[4] = {};
#pragma unroll 4
    for (int k = 0; k < 128; k++) {
        float wv = Wos[k][c];
        acc[0] += Att[rq*4+0][k] * wv;
        acc[1] += Att[rq*4+1][k] * wv;
        acc[2] += Att[rq*4+2][k] * wv;
        acc[3] += Att[rq*4+3][k] * wv;
    }
    float thr = g_ts[l];
    int spikes = 0;
#pragma unroll
    for (int q = 0; q < 4; q++) {
        int rloc = rq*4 + q;
        float st = 0.f;
        {
            int cnt = qcnt[rloc];
            const short* lst = ql[rloc];
            const float* at = g_At[l] + col0 + c;
            for (int i2 = 0; i2 < cnt; i2++)
                st += at[(int)lst[i2] * DS_];
        }
        int rr = row0 + rloc;
        int ci = col0 + c;
        float upd = acc[q] + bo[l*DS_ + ci] + st;
        float v = g_sv[l][rr*DS_ + ci] * DECAY_F + upd;
        float sp = (v >= thr) ? 1.f : 0.f;
        hdst[rr*DS_ + ci] = sp;
        g_sv[l][rr*DS_ + ci] = v * (1.f - sp);
        spikes += (v >= thr) ? 1 : 0;
    }
    sred[tid] = spikes; __syncthreads();
    for (int s = 128; s > 0; s >>= 1) { if (tid < s) sred[tid] += sred[tid+s]; __syncthreads(); }
    if (tid == 0) atomicAdd(&g_cnt1, (unsigned)sred[0]);
}

// ---------------- out_pot = h2@C.T (sparse) ; LIF2 ----------------
__global__ void __launch_bounds__(256)
k_e(int l, int par) {
    __shared__ short ql[8][128];
    __shared__ int qcnt[8];
    __shared__ int sred[256];
    const int tid = threadIdx.x;
    const int row0 = blockIdx.x * 8;
    const float* hnew = g_hbuf[l][1 - par];
    const int wrp = tid >> 5, lane = tid & 31;
    if (wrp < 8) {
        int base = 0;
        const float* hr = hnew + (size_t)(row0 + wrp)*DS_;
#pragma unroll
        for (int c4 = 0; c4 < 4; c4++) {
            float v = hr[c4*32 + lane];
            unsigned mask = __ballot_sync(0xffffffffu, v != 0.f);
            if (v != 0.f)
                ql[wrp][base + __popc(mask & ((1u<<lane)-1u))] = (short)(c4*32 + lane);
            base += __popc(mask);
        }
        if (lane == 0) qcnt[wrp] = base;
    }
    __syncthreads();
    const int c = tid;
    const float* ct = g_Ct[l] + c;
    float thr = g_to[l];
    int spikes = 0;
#pragma unroll 1
    for (int r = 0; r < 8; r++) {
        float acc = 0.f;
        int cnt = qcnt[r];
        const short* lst = ql[r];
        for (int i = 0; i < cnt; i++)
            acc += ct[(int)lst[i] * DM_];
        int gi = (row0 + r)*DM_ + c;
        float v = g_ov[l][gi] * DECAY_F + acc;
        float sp = (v >= thr) ? 1.f : 0.f;
        g_ov[l][gi] = v * (1.f - sp);
        if (l == 0) g_x[gi] = sp;
        else        g_tsum[gi] += sp * 0.125f;
        spikes += (v >= thr) ? 1 : 0;
    }
    sred[tid] = spikes; __syncthreads();
    for (int s = 128; s > 0; s >>= 1) { if (tid < s) sred[tid] += sred[tid+s]; __syncthreads(); }
    if (tid == 0) atomicAdd(&g_cnt2, (unsigned)sred[0]);
}

// ---------------- logits via bf16 split tensor cores (A converted inline) ----------------
__global__ void __launch_bounds__(256)
k_logits_mma(float* __restrict__ out) {
    __shared__ __align__(16) __nv_bfloat16 As[128][48];
    __shared__ __align__(16) __nv_bfloat16 Bs[128][48];
    const int tid = threadIdx.x;
    const int wid = tid >> 5;
    const int wm = wid & 1;
    const int wn = wid >> 1;
    const int row0 = blockIdx.x * 128;
    const int col0 = blockIdx.y * 128;

    wmma::fragment<wmma::accumulator, 16, 16, 16, float> acc[4][2];
#pragma unroll
    for (int i = 0; i < 4; i++)
#pragma unroll
        for (int j = 0; j < 2; j++)
            wmma::fill_fragment(acc[i][j], 0.f);

    const int lr = tid >> 1;
    const int lh = (tid & 1) * 16;

    for (int c = 0; c < 17; c++) {
        __nv_bfloat16 abuf[16];
        uint4 b0, b1;
        if (c < 16) {
            int koff = (c & 7) * 32;
            const float* af = g_tsum + (size_t)(row0+lr)*DM_ + koff + lh;
#pragma unroll
            for (int u = 0; u < 4; u++) {
                float4 f = *reinterpret_cast<const float4*>(af + u*4);
                abuf[u*4+0] = __float2bfloat16(f.x);
                abuf[u*4+1] = __float2bfloat16(f.y);
                abuf[u*4+2] = __float2bfloat16(f.z);
                abuf[u*4+3] = __float2bfloat16(f.w);
            }
            const __nv_bfloat16* bsrc = ((c < 8) ? g_Whi : g_Wlo) + (size_t)(col0+lr)*DM_ + koff + lh;
            b0 = *reinterpret_cast<const uint4*>(bsrc);
            b1 = *reinterpret_cast<const uint4*>(bsrc + 8);
        } else {
#pragma unroll
            for (int u = 0; u < 16; u++) abuf[u] = __float2bfloat16(0.f);
            if (lh == 0) { abuf[0] = __float2bfloat16(1.f); abuf[1] = __float2bfloat16(1.f); }
            const __nv_bfloat16* bsrc = g_Bext + (size_t)(col0+lr)*32 + lh;
            b0 = *reinterpret_cast<const uint4*>(bsrc);
            b1 = *reinterpret_cast<const uint4*>(bsrc + 8);
        }
        __syncthreads();
        *reinterpret_cast<uint4*>(&As[lr][lh])     = reinterpret_cast<uint4*>(abuf)[0];
        *reinterpret_cast<uint4*>(&As[lr][lh + 8]) = reinterpret_cast<uint4*>(abuf)[1];
        *reinterpret_cast<uint4*>(&Bs[lr][lh])     = b0;
        *reinterpret_cast<uint4*>(&Bs[lr][lh + 8]) = b1;
        __syncthreads();
#pragma unroll
        for (int kk = 0; kk < 32; kk += 16) {
            wmma::fragment<wmma::matrix_a, 16, 16, 16, __nv_bfloat16, wmma::row_major> af[4];
            wmma::fragment<wmma::matrix_b, 16, 16, 16, __nv_bfloat16, wmma::col_major> bf[2];
#pragma unroll
            for (int i = 0; i < 4; i++)
                wmma::load_matrix_sync(af[i], &As[wm*64 + i*16][kk], 48);
#pragma unroll
            for (int j = 0; j < 2; j++)
                wmma::load_matrix_sync(bf[j], &Bs[wn*32 + j*16][kk], 48);
#pragma unroll
            for (int i = 0; i < 4; i++)
#pragma unroll
                for (int j = 0; j < 2; j++)
                    wmma::mma_sync(acc[i][j], af[i], bf[j], acc[i][j]);
        }
    }
#pragma unroll
    for (int i = 0; i < 4; i++)
#pragma unroll
        for (int j = 0; j < 2; j++) {
            size_t r = row0 + wm*64 + i*16;
            size_t cc = col0 + wn*32 + j*16;
            wmma::store_matrix_sync(&out[r*VOC_ + cc], acc[i][j], VOC_, wmma::mem_row_major);
        }
}

// ---------------- launch ----------------
extern "C" void kernel_launch(void* const* d_in, const int* in_sizes, int n_in,
                              void* d_out, int out_size) {
    const int*   ids  = (const int*)d_in[0];
    const float* emb  = (const float*)d_in[1];
    const float* Amat = (const float*)d_in[2];
    const float* Cmat = (const float*)d_in[3];
    const float* Wq   = (const float*)d_in[4];
    const float* bq   = (const float*)d_in[5];
    const float* Wkv  = (const float*)d_in[6];
    const float* bkv  = (const float*)d_in[7];
    const float* Wo   = (const float*)d_in[8];
    const float* bo   = (const float*)d_in[9];
    const float* Wout = (const float*)d_in[10];
    const float* bout = (const float*)d_in[11];
    float* out = (float*)d_out;

    setup_kernel<<<2048, 256>>>(ids, emb, Wq, Amat, Wo, Cmat, Wkv, Wout, bout);
    k_kv0<<<dim3(4, 16), 512>>>(Wkv, bkv);

    int prev = -1;
    for (int t = 0; t < T_; t++) {
        int par = t & 1;
        for (int l = 0; l < NL_; l++) {
            if (l == 1) k_kv_sp<<<128, 256>>>(bkv);
            k_attn<<<dim3(32, 4), 512>>>(l, prev, par, bq);
            k_d   <<<dim3(4, 32), 256>>>(l, par, bo);
            k_e   <<<128, 256>>>(l, par);
            prev = l;
        }
    }
    k_logits_mma<<<dim3(8, 250), 256>>>(out);
}